// round 14
// baseline (speedup 1.0000x reference)
#include <cuda_runtime.h>

#define HW 16384
#define TILE_W 32
#define TILE_H 16
#define XSTR 34            // EVEN padded row stride -> 8B-aligned pairs
#define CSTR 612           // 18 * 34
#define XT_SZ_H 19584      // 32 channels * 612
#define XT_HALF 9792       // 16 channels * 612

typedef unsigned long long ull;

// ---------------- f32x2 helpers ------------------------------------------------
__device__ __forceinline__ ull pk2(float lo, float hi) {
    ull r; asm("mov.b64 %0,{%1,%2};" : "=l"(r) : "f"(lo), "f"(hi)); return r;
}
__device__ __forceinline__ ull dup2(float v) { return pk2(v, v); }
__device__ __forceinline__ void upk2(ull v, float& lo, float& hi) {
    asm("mov.b64 {%0,%1},%2;" : "=f"(lo), "=f"(hi) : "l"(v));
}
__device__ __forceinline__ ull f2fma(ull a, ull b, ull c) {
    ull d; asm("fma.rn.f32x2 %0,%1,%2,%3;" : "=l"(d) : "l"(a), "l"(b), "l"(c)); return d;
}
__device__ __forceinline__ ull f2add(ull a, ull b) {
    ull d; asm("add.rn.f32x2 %0,%1,%2;" : "=l"(d) : "l"(a), "l"(b)); return d;
}
__device__ __forceinline__ ull f2relu(ull v) {
    float lo, hi; upk2(v, lo, hi);
    return pk2(fmaxf(lo, 0.f), fmaxf(hi, 0.f));
}

// ---------------- cp.async helpers ---------------------------------------------
__device__ __forceinline__ void cpa4(void* sdst, const void* gsrc, int szbytes) {
    unsigned saddr = (unsigned)__cvta_generic_to_shared(sdst);
    asm volatile("cp.async.ca.shared.global [%0], [%1], 4, %2;"
                 :: "r"(saddr), "l"(gsrc), "r"(szbytes));
}
__device__ __forceinline__ void cpa_commit() {
    asm volatile("cp.async.commit_group;");
}
__device__ __forceinline__ void cpa_wait1() {
    asm volatile("cp.async.wait_group 1;" ::: "memory");
}
__device__ __forceinline__ void cpa_wait0() {
    asm volatile("cp.async.wait_group 0;" ::: "memory");
}

// ---------------- scratch ----------------------------------------------------
__device__ float g_wraw[8 * 72 * HW];
__device__ float g_xv[8 * 64 * HW];
__device__ float g_gnpart[256 * 16];
__device__ float g_gnstat[64 * 2];
__device__ float g_chanpart[256 * 64];
__device__ float g_yscale[512];
__device__ unsigned g_ctrA = 0;
__device__ unsigned g_ctrB = 0;

// ---------------- passA smem layout (float offsets), per half ----------------
#define WKd 0              // 2304: oc-paired key weights
#define WE1 2304           // 1024
#define WE2 3328           // 576
#define BE2 3904           // 36 (pad 40)
#define WC1 3944           // 1024
#define XTA 4968
#define SMEMA ((XTA + XT_SZ_H) * 4)

__global__ void __launch_bounds__(256, 2) passA(
    const float* __restrict__ x, const float* __restrict__ wkey,
    const float* __restrict__ we1, const float* __restrict__ we2,
    const float* __restrict__ be2, const float* __restrict__ wc1)
{
    extern __shared__ float sm[];
    __shared__ bool isLast;
    const int tid = threadIdx.x;
    const int b = blockIdx.z >> 1, half = blockIdx.z & 1;
    const int ty0 = blockIdx.y * TILE_H, tx0 = blockIdx.x * TILE_W;
    const float* xb = x + (size_t)b * 64 * HW + ((size_t)half << 19);
    float* xt = sm + XTA;

    // ---- group 0: tile channels 0..15 + all weights ----
    for (int i = tid; i < XT_HALF; i += 256) {
        int c = i / CSTR, r = i - c * CSTR, yy = r / XSTR, xx = r - yy * XSTR;
        int gy = ty0 + yy - 1, gx = tx0 + xx - 1;
        bool ok = ((unsigned)gy < 128u) && ((unsigned)gx < 128u);
        int cgy = min(max(gy, 0), 127), cgx = min(max(gx, 0), 127);
        cpa4(xt + i, xb + (c << 14) + (cgy << 7) + cgx, ok ? 4 : 0);
    }
    for (int i = tid; i < 2304; i += 256) {
        int w18 = i / 18, r = i - w18 * 18;
        int t = r >> 1, s = r & 1;
        int ocp = w18 & 3, gci = w18 >> 2;
        int ci = gci & 7, g4 = gci >> 3;
        cpa4(sm + WKd + i, wkey + (half * 32 + g4 * 8 + ocp * 2 + s) * 72 + ci * 9 + t, 4);
    }
    for (int i = tid; i < 1024; i += 256) {
        int o = i >> 6, ic = i & 63;
        cpa4(sm + WE1 + (((ic >> 1) * 16 + o) << 1) + (ic & 1), we1 + half * 1024 + i, 4);
    }
    for (int i = tid; i < 576; i += 256) cpa4(sm + WE2 + i, we2 + half * 576 + i, 4);
    if (tid < 36) cpa4(sm + BE2 + tid, be2 + half * 36 + tid, 4);
    for (int i = tid; i < 1024; i += 256) cpa4(sm + WC1 + i, wc1 + half * 1024 + i, 4);
    cpa_commit();

    // ---- group 1: tile channels 16..31 ----
    for (int i = XT_HALF + tid; i < XT_SZ_H; i += 256) {
        int c = i / CSTR, r = i - c * CSTR, yy = r / XSTR, xx = r - yy * XSTR;
        int gy = ty0 + yy - 1, gx = tx0 + xx - 1;
        bool ok = ((unsigned)gy < 128u) && ((unsigned)gx < 128u);
        int cgy = min(max(gy, 0), 127), cgx = min(max(gx, 0), 127);
        cpa4(xt + i, xb + (c << 14) + (cgy << 7) + cgx, ok ? 4 : 0);
    }
    cpa_commit();

    cpa_wait1();
    __syncthreads();

    const int lty = tid >> 4, lx0 = (tid & 15) << 1;
    const int pix = ((ty0 + lty) << 7) + tx0 + lx0;

    ull acc2[16];
    #pragma unroll
    for (int o = 0; o < 16; o++) acc2[o] = 0ull;

    #pragma unroll 1
    for (int g4 = 0; g4 < 4; g4++) {
        if (g4 == 2) {
            cpa_wait0();
            __syncthreads();
        }
        ull kk2[8];
        #pragma unroll
        for (int i = 0; i < 8; i++) kk2[i] = 0ull;

        #pragma unroll 1
        for (int ci = 0; ci < 8; ci++) {
            const float* pb = xt + (g4 * 8 + ci) * CSTR + lty * XSTR + lx0;
            ull dp[12];
            #pragma unroll
            for (int dy = 0; dy < 3; dy++) {
                ull A = *(const ull*)(pb + dy * XSTR);
                ull B = *(const ull*)(pb + dy * XSTR + 2);
                float p0, p1, p2, p3;
                upk2(A, p0, p1); upk2(B, p2, p3);
                dp[dy * 4 + 0] = dup2(p0); dp[dy * 4 + 1] = dup2(p1);
                dp[dy * 4 + 2] = dup2(p2); dp[dy * 4 + 3] = dup2(p3);
            }
            const ull* wd = (const ull*)(sm + WKd) + (g4 * 8 + ci) * 36;
            #pragma unroll
            for (int ocp = 0; ocp < 4; ocp++) {
                ull kA = kk2[ocp], kB = kk2[4 + ocp];
                #pragma unroll
                for (int dy = 0; dy < 3; dy++)
                    #pragma unroll
                    for (int dx = 0; dx < 3; dx++) {
                        ull w = wd[ocp * 9 + dy * 3 + dx];
                        kA = f2fma(dp[dy * 4 + dx],     w, kA);
                        kB = f2fma(dp[dy * 4 + dx + 1], w, kB);
                    }
                kk2[ocp] = kA; kk2[4 + ocp] = kB;
            }
        }
        float k0[8], k1[8];
        #pragma unroll
        for (int ocp = 0; ocp < 4; ocp++) {
            upk2(kk2[ocp],     k0[2 * ocp], k0[2 * ocp + 1]);
            upk2(kk2[4 + ocp], k1[2 * ocp], k1[2 * ocp + 1]);
        }
        #pragma unroll 1
        for (int ci = 0; ci < 8; ci++) {
            const float* ctr = xt + (g4 * 8 + ci) * CSTR + (lty + 1) * XSTR + lx0 + 1;
            ull xc2 = pk2(ctr[0], ctr[1]);
            ull kv2 = pk2(fmaxf(k0[ci], 0.f), fmaxf(k1[ci], 0.f));
            const float2* w1 = (const float2*)(sm + WE1 + ((g4 * 8 + ci) << 5));
            #pragma unroll
            for (int o = 0; o < 16; o++) {
                float2 w = w1[o];
                acc2[o] = f2fma(xc2, dup2(w.x), f2fma(kv2, dup2(w.y), acc2[o]));
            }
        }
    }
    #pragma unroll
    for (int o = 0; o < 16; o++) acc2[o] = f2relu(acc2[o]);

    float lsum[4], lsq[4];
    #pragma unroll
    for (int g4 = 0; g4 < 4; g4++) {
        ull s2 = 0ull, q2 = 0ull;
        #pragma unroll
        for (int j = 0; j < 9; j++) {
            const int o2l = g4 * 9 + j;
            const float4* w2 = (const float4*)(sm + WE2 + o2l * 16);
            ull a2 = dup2(sm[BE2 + o2l]);
            #pragma unroll
            for (int qq = 0; qq < 4; qq++) {
                float4 w = w2[qq];
                a2 = f2fma(acc2[qq * 4 + 0], dup2(w.x), a2);
                a2 = f2fma(acc2[qq * 4 + 1], dup2(w.y), a2);
                a2 = f2fma(acc2[qq * 4 + 2], dup2(w.z), a2);
                a2 = f2fma(acc2[qq * 4 + 3], dup2(w.w), a2);
            }
            *(ull*)(g_wraw + (((size_t)b * 72 + half * 36 + o2l) << 14) + pix) = a2;
            s2 = f2add(s2, a2);
            q2 = f2fma(a2, a2, q2);
        }
        float slo, shi, qlo, qhi;
        upk2(s2, slo, shi); upk2(q2, qlo, qhi);
        lsum[g4] = slo + shi; lsq[g4] = qlo + qhi;
    }

    {
        ull xin2[32];
        #pragma unroll
        for (int ic = 0; ic < 32; ic++) {
            const float* ctr = xt + ic * CSTR + (lty + 1) * XSTR + lx0 + 1;
            xin2[ic] = pk2(ctr[0], ctr[1]);
        }
        #pragma unroll 1
        for (int oc = 0; oc < 32; oc++) {
            const float4* w = (const float4*)(sm + WC1 + (oc << 5));
            ull a2 = 0ull;
            #pragma unroll
            for (int qq = 0; qq < 8; qq++) {
                float4 wv = w[qq];
                a2 = f2fma(xin2[qq * 4 + 0], dup2(wv.x), a2);
                a2 = f2fma(xin2[qq * 4 + 1], dup2(wv.y), a2);
                a2 = f2fma(xin2[qq * 4 + 2], dup2(wv.z), a2);
                a2 = f2fma(xin2[qq * 4 + 3], dup2(wv.w), a2);
            }
            *(ull*)(g_xv + (((size_t)b * 64 + half * 32 + oc) << 14) + pix) = a2;
        }
    }

    __syncthreads();
    #pragma unroll
    for (int off = 16; off; off >>= 1)
        #pragma unroll
        for (int g4 = 0; g4 < 4; g4++) {
            lsum[g4] += __shfl_xor_sync(0xffffffffu, lsum[g4], off);
            lsq[g4]  += __shfl_xor_sync(0xffffffffu, lsq[g4],  off);
        }
    const int wid = tid >> 5, lane = tid & 31;
    if (lane == 0) {
        #pragma unroll
        for (int g4 = 0; g4 < 4; g4++) {
            sm[wid * 8 + g4] = lsum[g4];
            sm[wid * 8 + 4 + g4] = lsq[g4];
        }
    }
    __syncthreads();
    if (tid < 8) {
        float s = 0.f;
        #pragma unroll
        for (int w = 0; w < 8; w++) s += sm[w * 8 + tid];
        int slot = (b * 32 + blockIdx.y * 4 + blockIdx.x) * 16;
        int e = (tid < 4) ? (half * 4 + tid) : (8 + half * 4 + tid - 4);
        g_gnpart[slot + e] = s;
    }
    __syncthreads();

    if (tid == 0) {
        __threadfence();
        unsigned old = atomicAdd(&g_ctrA, 1u);
        isLast = (old == 511u);
    }
    __syncthreads();
    if (isLast) {
        int idx = tid >> 2, k = tid & 3;
        int bb = idx >> 3, gg = idx & 7;
        float s = 0.f, q = 0.f;
        #pragma unroll
        for (int t = 0; t < 8; t++) {
            int tile = k * 8 + t;
            s += *(volatile const float*)&g_gnpart[(bb * 32 + tile) * 16 + gg];
            q += *(volatile const float*)&g_gnpart[(bb * 32 + tile) * 16 + 8 + gg];
        }
        #pragma unroll
        for (int off = 2; off; off >>= 1) {
            s += __shfl_xor_sync(0xffffffffu, s, off);
            q += __shfl_xor_sync(0xffffffffu, q, off);
        }
        if (k == 0) {
            const float inv_n = 1.f / 147456.f;
            float m = s * inv_n;
            float v = fmaf(q, inv_n, -m * m);
            g_gnstat[idx * 2] = m;
            g_gnstat[idx * 2 + 1] = rsqrtf(v + 1e-5f);
        }
        if (tid == 0) g_ctrA = 0;
    }
}

// ---------------- passB ------------------------------------------------------------
#define ST  0
#define SC  8
#define GW  264
#define GB  300
#define XTB 336
#define SMEMB ((XTB + XT_SZ_H) * 4)

__global__ void __launch_bounds__(256, 2) passB(
    float* __restrict__ out, const float* __restrict__ gnw,
    const float* __restrict__ gnb, const float* __restrict__ wdu1,
    const float* __restrict__ wdu2)
{
    extern __shared__ float sm[];
    __shared__ bool isLast;
    __shared__ float smm[512], t4s[32];
    const int tid = threadIdx.x;
    const int b = blockIdx.z >> 1, half = blockIdx.z & 1;
    const int ty0 = blockIdx.y * TILE_H, tx0 = blockIdx.x * TILE_W;

    float* xt = sm + XTB;
    const float* xvb = g_xv + (size_t)b * 64 * HW + ((size_t)half << 19);
    for (int i = tid; i < XT_HALF; i += 256) {
        int c = i / CSTR, r = i - c * CSTR, yy = r / XSTR, xx = r - yy * XSTR;
        int gy = ty0 + yy - 1, gx = tx0 + xx - 1;
        bool ok = ((unsigned)gy < 128u) && ((unsigned)gx < 128u);
        int cgy = min(max(gy, 0), 127), cgx = min(max(gx, 0), 127);
        cpa4(xt + i, xvb + (c << 14) + (cgy << 7) + cgx, ok ? 4 : 0);
    }
    cpa_commit();
    for (int i = XT_HALF + tid; i < XT_SZ_H; i += 256) {
        int c = i / CSTR, r = i - c * CSTR, yy = r / XSTR, xx = r - yy * XSTR;
        int gy = ty0 + yy - 1, gx = tx0 + xx - 1;
        bool ok = ((unsigned)gy < 128u) && ((unsigned)gx < 128u);
        int cgy = min(max(gy, 0), 127), cgx = min(max(gx, 0), 127);
        cpa4(xt + i, xvb + (c << 14) + (cgy << 7) + cgx, ok ? 4 : 0);
    }
    cpa_commit();

    if (tid < 8) sm[ST + tid] = g_gnstat[b * 16 + half * 8 + tid];
    if (tid < 256) sm[SC + tid] = 0.f;
    if (tid >= 128 && tid < 164) sm[GW + tid - 128] = gnw[half * 36 + tid - 128];
    if (tid >= 192 && tid < 228) sm[GB + tid - 192] = gnb[half * 36 + tid - 192];

    cpa_wait1();
    __syncthreads();

    const int lty = tid >> 4, lx0 = (tid & 15) << 1;
    const int pix = ((ty0 + lty) << 7) + tx0 + lx0;
    const int wid = tid >> 5;

    #pragma unroll 1
    for (int g4 = 0; g4 < 4; g4++) {
        if (g4 == 2) {
            cpa_wait0();
            __syncthreads();
        }
        float mean = sm[ST + g4 * 2], rstd = sm[ST + g4 * 2 + 1];
        ull bw[9];
        #pragma unroll
        for (int t = 0; t < 9; t++) {
            int o2 = half * 36 + g4 * 9 + t;
            float2 raw = *(const float2*)(g_wraw + (((size_t)b * 72 + o2) << 14) + pix);
            float gw = sm[GW + g4 * 9 + t], gb = sm[GB + g4 * 9 + t];
            float w0 = fmaf((raw.x - mean) * rstd, gw, gb);
            float w1 = fmaf((raw.y - mean) * rstd, gw, gb);
            bw[t] = pk2(w0, w1);
        }
        #pragma unroll 1
        for (int cc = 0; cc < 8; cc++) {
            int cl = g4 * 8 + cc;
            const float* pb = xt + cl * CSTR + lty * XSTR + lx0;
            ull a2 = 0ull;
            #pragma unroll
            for (int dy = 0; dy < 3; dy++) {
                ull A = *(const ull*)(pb + dy * XSTR);
                ull B = *(const ull*)(pb + dy * XSTR + 2);
                float a0, a1, b0, b1;
                upk2(A, a0, a1); upk2(B, b0, b1);
                a2 = f2fma(A,           bw[dy * 3 + 0], a2);
                a2 = f2fma(pk2(a1, b0), bw[dy * 3 + 1], a2);
                a2 = f2fma(B,           bw[dy * 3 + 2], a2);
            }
            *(ull*)(out + (((size_t)b * 64 + half * 32 + cl) << 14) + pix) = a2;
            float a0, a1; upk2(a2, a0, a1);
            // warp-uniform-address atomicAdd -> ptxas REDUX.SUM aggregate
            // (one aggregated atomic per warp per (g4,cc): deterministic)
            atomicAdd(&sm[SC + wid * 32 + cl], a0 + a1);
        }
    }
    __syncthreads();
    if (tid < 32) {
        float s = 0.f;
        #pragma unroll
        for (int w = 0; w < 8; w++) s += sm[SC + w * 32 + tid];
        g_chanpart[(b * 32 + blockIdx.y * 4 + blockIdx.x) * 64 + half * 32 + tid] = s;
    }
    __syncthreads();

    if (tid == 0) {
        __threadfence();
        unsigned old = atomicAdd(&g_ctrB, 1u);
        isLast = (old == 511u);
    }
    __syncthreads();
    if (isLast) {
        #pragma unroll
        for (int rep = 0; rep < 2; rep++) {
            int idx = rep * 256 + tid;
            int bb = idx >> 6, c = idx & 63;
            float s = 0.f;
            #pragma unroll
            for (int t = 0; t < 32; t++)
                s += *(volatile const float*)&g_chanpart[(bb * 32 + t) * 64 + c];
            smm[idx] = s * (1.f / 16384.f);
        }
        __syncthreads();
        if (tid < 32) {
            int bb = tid >> 2, h = tid & 3;
            float a = 0.f;
            #pragma unroll
            for (int i = 0; i < 64; i++)
                a = fmaf(smm[bb * 64 + i], __ldg(wdu1 + h * 64 + i), a);
            t4s[tid] = fmaxf(a, 0.f);
        }
        __syncthreads();
        #pragma unroll
        for (int rep = 0; rep < 2; rep++) {
            int idx = rep * 256 + tid;
            int bb = idx >> 6, c = idx & 63;
            float a = 0.f;
            #pragma unroll
            for (int j = 0; j < 4; j++)
                a = fmaf(t4s[bb * 4 + j], __ldg(wdu2 + c * 4 + j), a);
            g_yscale[idx] = 1.f / (1.f + expf(-a));
        }
        if (tid == 0) g_ctrB = 0;
    }
}

// ---------------- final scale -----------------------------------------------------
__global__ void scaleK(float* __restrict__ out)
{
    int i = blockIdx.x * blockDim.x + threadIdx.x;
    float4* p = (float4*)out;
    float s = g_yscale[i >> 12];
    float4 v = p[i];
    v.x *= s; v.y *= s; v.z *= s; v.w *= s;
    p[i] = v;
}

// ---------------- launcher ---------------------------------------------------------
extern "C" void kernel_launch(void* const* d_in, const int* in_sizes, int n_in,
                              void* d_out, int out_size)
{
    const float* x    = (const float*)d_in[0];
    const float* wkey = (const float*)d_in[1];
    const float* we1  = (const float*)d_in[2];
    const float* we2  = (const float*)d_in[3];
    const float* be2  = (const float*)d_in[4];
    const float* gnw  = (const float*)d_in[5];
    const float* gnb  = (const float*)d_in[6];
    const float* wc1  = (const float*)d_in[7];
    const float* wdu1 = (const float*)d_in[8];
    const float* wdu2 = (const float*)d_in[9];
    float* out = (float*)d_out;

    cudaFuncSetAttribute(passA, cudaFuncAttributeMaxDynamicSharedMemorySize, SMEMA);
    cudaFuncSetAttribute(passB, cudaFuncAttributeMaxDynamicSharedMemorySize, SMEMB);

    dim3 grid(4, 8, 16);
    passA<<<grid, 256, SMEMA>>>(x, wkey, we1, we2, be2, wc1);
    passB<<<grid, 256, SMEMB>>>(out, gnw, gnb, wdu1, wdu2);
    scaleK<<<8192, 256>>>(out);
}

// round 15
// speedup vs baseline: 1.6970x; 1.6970x over previous
#include <cuda_runtime.h>

#define HW 16384
#define TILE_W 32
#define TILE_H 16
#define XSTR 34            // EVEN padded row stride -> 8B-aligned pairs
#define CSTR 612           // 18 * 34
#define XT_SZ_H 19584      // 32 channels * 612
#define XT_HALF 9792       // 16 channels * 612

typedef unsigned long long ull;

// ---------------- f32x2 helpers ------------------------------------------------
__device__ __forceinline__ ull pk2(float lo, float hi) {
    ull r; asm("mov.b64 %0,{%1,%2};" : "=l"(r) : "f"(lo), "f"(hi)); return r;
}
__device__ __forceinline__ ull dup2(float v) { return pk2(v, v); }
__device__ __forceinline__ void upk2(ull v, float& lo, float& hi) {
    asm("mov.b64 {%0,%1},%2;" : "=f"(lo), "=f"(hi) : "l"(v));
}
__device__ __forceinline__ ull f2fma(ull a, ull b, ull c) {
    ull d; asm("fma.rn.f32x2 %0,%1,%2,%3;" : "=l"(d) : "l"(a), "l"(b), "l"(c)); return d;
}
__device__ __forceinline__ ull f2add(ull a, ull b) {
    ull d; asm("add.rn.f32x2 %0,%1,%2;" : "=l"(d) : "l"(a), "l"(b)); return d;
}
__device__ __forceinline__ ull f2relu(ull v) {
    float lo, hi; upk2(v, lo, hi);
    return pk2(fmaxf(lo, 0.f), fmaxf(hi, 0.f));
}

// ---------------- cp.async helpers ---------------------------------------------
__device__ __forceinline__ void cpa4(void* sdst, const void* gsrc, int szbytes) {
    unsigned saddr = (unsigned)__cvta_generic_to_shared(sdst);
    asm volatile("cp.async.ca.shared.global [%0], [%1], 4, %2;"
                 :: "r"(saddr), "l"(gsrc), "r"(szbytes));
}
__device__ __forceinline__ void cpa_commit() {
    asm volatile("cp.async.commit_group;");
}
__device__ __forceinline__ void cpa_wait1() {
    asm volatile("cp.async.wait_group 1;" ::: "memory");
}
__device__ __forceinline__ void cpa_wait0() {
    asm volatile("cp.async.wait_group 0;" ::: "memory");
}

// ---------------- scratch ----------------------------------------------------
__device__ float g_wraw[8 * 72 * HW];
__device__ float g_xv[8 * 64 * HW];
__device__ float g_gnpart[256 * 16];
__device__ float g_gnstat[64 * 2];
__device__ float g_chanpart[256 * 64];
__device__ float g_yscale[512];
__device__ unsigned g_ctrA = 0;
__device__ unsigned g_ctrB = 0;

// ---------------- passA smem layout (float offsets), per half ----------------
// WE1 now o-PAIR interleaved per input channel m:
//   sm[WE1 + m*32 + p*4 + {0,1,2,3}] = (wx_{2p}, wx_{2p+1}, wk_{2p}, wk_{2p+1})
#define WKd 0              // 2304: oc-paired key weights
#define WE1 2304           // 1024
#define WE2 3328           // 576
#define BE2 3904           // 36 (pad 40)
#define WC1 3944           // 1024
#define XTA 4968
#define SMEMA ((XTA + XT_SZ_H) * 4)

__global__ void __launch_bounds__(256, 2) passA(
    const float* __restrict__ x, const float* __restrict__ wkey,
    const float* __restrict__ we1, const float* __restrict__ we2,
    const float* __restrict__ be2, const float* __restrict__ wc1)
{
    extern __shared__ float sm[];
    __shared__ bool isLast;
    const int tid = threadIdx.x;
    const int b = blockIdx.z >> 1, half = blockIdx.z & 1;
    const int ty0 = blockIdx.y * TILE_H, tx0 = blockIdx.x * TILE_W;
    const float* xb = x + (size_t)b * 64 * HW + ((size_t)half << 19);
    float* xt = sm + XTA;

    // ---- group 0: tile channels 0..15 + all weights ----
    for (int i = tid; i < XT_HALF; i += 256) {
        int c = i / CSTR, r = i - c * CSTR, yy = r / XSTR, xx = r - yy * XSTR;
        int gy = ty0 + yy - 1, gx = tx0 + xx - 1;
        bool ok = ((unsigned)gy < 128u) && ((unsigned)gx < 128u);
        int cgy = min(max(gy, 0), 127), cgx = min(max(gx, 0), 127);
        cpa4(xt + i, xb + (c << 14) + (cgy << 7) + cgx, ok ? 4 : 0);
    }
    for (int i = tid; i < 2304; i += 256) {
        int w18 = i / 18, r = i - w18 * 18;
        int t = r >> 1, s = r & 1;
        int ocp = w18 & 3, gci = w18 >> 2;
        int ci = gci & 7, g4 = gci >> 3;
        cpa4(sm + WKd + i, wkey + (half * 32 + g4 * 8 + ocp * 2 + s) * 72 + ci * 9 + t, 4);
    }
    // e1 weights, o-pair interleaved
    for (int i = tid; i < 1024; i += 256) {
        int m = i >> 5, r = i & 31, p = r >> 2, q = r & 3;
        int o = 2 * p + (q & 1), s = q >> 1;
        cpa4(sm + WE1 + i, we1 + half * 1024 + o * 64 + m * 2 + s, 4);
    }
    for (int i = tid; i < 576; i += 256) cpa4(sm + WE2 + i, we2 + half * 576 + i, 4);
    if (tid < 36) cpa4(sm + BE2 + tid, be2 + half * 36 + tid, 4);
    for (int i = tid; i < 1024; i += 256) cpa4(sm + WC1 + i, wc1 + half * 1024 + i, 4);
    cpa_commit();

    // ---- group 1: tile channels 16..31 ----
    for (int i = XT_HALF + tid; i < XT_SZ_H; i += 256) {
        int c = i / CSTR, r = i - c * CSTR, yy = r / XSTR, xx = r - yy * XSTR;
        int gy = ty0 + yy - 1, gx = tx0 + xx - 1;
        bool ok = ((unsigned)gy < 128u) && ((unsigned)gx < 128u);
        int cgy = min(max(gy, 0), 127), cgx = min(max(gx, 0), 127);
        cpa4(xt + i, xb + (c << 14) + (cgy << 7) + cgx, ok ? 4 : 0);
    }
    cpa_commit();

    cpa_wait1();
    __syncthreads();

    const int lty = tid >> 4, lx0 = (tid & 15) << 1;
    const int pix = ((ty0 + lty) << 7) + tx0 + lx0;

    // e1 accumulators: OUTPUT-pair packed, per pixel
    // aP0[p] = (acc_{2p}, acc_{2p+1}) for pixel0 ; aP1[p] for pixel1
    ull aP0[8], aP1[8];
    #pragma unroll
    for (int p = 0; p < 8; p++) { aP0[p] = 0ull; aP1[p] = 0ull; }

    #pragma unroll 1
    for (int g4 = 0; g4 < 4; g4++) {
        if (g4 == 2) {
            cpa_wait0();
            __syncthreads();
        }
        ull kk2[8];
        #pragma unroll
        for (int i = 0; i < 8; i++) kk2[i] = 0ull;

        #pragma unroll 1
        for (int ci = 0; ci < 8; ci++) {
            const float* pb = xt + (g4 * 8 + ci) * CSTR + lty * XSTR + lx0;
            ull dp[12];
            #pragma unroll
            for (int dy = 0; dy < 3; dy++) {
                ull A = *(const ull*)(pb + dy * XSTR);
                ull B = *(const ull*)(pb + dy * XSTR + 2);
                float p0, p1, p2, p3;
                upk2(A, p0, p1); upk2(B, p2, p3);
                dp[dy * 4 + 0] = dup2(p0); dp[dy * 4 + 1] = dup2(p1);
                dp[dy * 4 + 2] = dup2(p2); dp[dy * 4 + 3] = dup2(p3);
            }
            const ull* wd = (const ull*)(sm + WKd) + (g4 * 8 + ci) * 36;
            #pragma unroll
            for (int ocp = 0; ocp < 4; ocp++) {
                ull kA = kk2[ocp], kB = kk2[4 + ocp];
                #pragma unroll
                for (int dy = 0; dy < 3; dy++)
                    #pragma unroll
                    for (int dx = 0; dx < 3; dx++) {
                        ull w = wd[ocp * 9 + dy * 3 + dx];
                        kA = f2fma(dp[dy * 4 + dx],     w, kA);
                        kB = f2fma(dp[dy * 4 + dx + 1], w, kB);
                    }
                kk2[ocp] = kA; kk2[4 + ocp] = kB;
            }
        }
        float k0[8], k1[8];
        #pragma unroll
        for (int ocp = 0; ocp < 4; ocp++) {
            upk2(kk2[ocp],     k0[2 * ocp], k0[2 * ocp + 1]);
            upk2(kk2[4 + ocp], k1[2 * ocp], k1[2 * ocp + 1]);
        }
        // e1: output-pair packed — weight pairs via LDS.128, 4 dups per ci
        #pragma unroll 1
        for (int ci = 0; ci < 8; ci++) {
            const float* ctr = xt + (g4 * 8 + ci) * CSTR + (lty + 1) * XSTR + lx0 + 1;
            ull dx0 = dup2(ctr[0]), dx1 = dup2(ctr[1]);
            ull dk0 = dup2(fmaxf(k0[ci], 0.f)), dk1 = dup2(fmaxf(k1[ci], 0.f));
            const ulonglong2* w1 = (const ulonglong2*)(sm + WE1 + ((g4 * 8 + ci) << 5));
            #pragma unroll
            for (int p = 0; p < 8; p++) {
                ulonglong2 w = w1[p];   // w.x = (wx_o, wx_o+1), w.y = (wk_o, wk_o+1)
                aP0[p] = f2fma(dx0, w.x, f2fma(dk0, w.y, aP0[p]));
                aP1[p] = f2fma(dx1, w.x, f2fma(dk1, w.y, aP1[p]));
            }
        }
    }
    // repack output-pair -> pixel-pair (acc2[o] = (a_o_px0, a_o_px1)), fused relu
    ull acc2[16];
    #pragma unroll
    for (int p = 0; p < 8; p++) {
        float a00, a01, a10, a11;
        upk2(aP0[p], a00, a01);
        upk2(aP1[p], a10, a11);
        acc2[2 * p]     = pk2(fmaxf(a00, 0.f), fmaxf(a10, 0.f));
        acc2[2 * p + 1] = pk2(fmaxf(a01, 0.f), fmaxf(a11, 0.f));
    }

    float lsum[4], lsq[4];
    #pragma unroll
    for (int g4 = 0; g4 < 4; g4++) {
        ull s2 = 0ull, q2 = 0ull;
        #pragma unroll
        for (int j = 0; j < 9; j++) {
            const int o2l = g4 * 9 + j;
            const float4* w2 = (const float4*)(sm + WE2 + o2l * 16);
            ull a2 = dup2(sm[BE2 + o2l]);
            #pragma unroll
            for (int qq = 0; qq < 4; qq++) {
                float4 w = w2[qq];
                a2 = f2fma(acc2[qq * 4 + 0], dup2(w.x), a2);
                a2 = f2fma(acc2[qq * 4 + 1], dup2(w.y), a2);
                a2 = f2fma(acc2[qq * 4 + 2], dup2(w.z), a2);
                a2 = f2fma(acc2[qq * 4 + 3], dup2(w.w), a2);
            }
            *(ull*)(g_wraw + (((size_t)b * 72 + half * 36 + o2l) << 14) + pix) = a2;
            s2 = f2add(s2, a2);
            q2 = f2fma(a2, a2, q2);
        }
        float slo, shi, qlo, qhi;
        upk2(s2, slo, shi); upk2(q2, qlo, qhi);
        lsum[g4] = slo + shi; lsq[g4] = qlo + qhi;
    }

    {
        ull xin2[32];
        #pragma unroll
        for (int ic = 0; ic < 32; ic++) {
            const float* ctr = xt + ic * CSTR + (lty + 1) * XSTR + lx0 + 1;
            xin2[ic] = pk2(ctr[0], ctr[1]);
        }
        #pragma unroll 1
        for (int oc = 0; oc < 32; oc++) {
            const float4* w = (const float4*)(sm + WC1 + (oc << 5));
            ull a2 = 0ull;
            #pragma unroll
            for (int qq = 0; qq < 8; qq++) {
                float4 wv = w[qq];
                a2 = f2fma(xin2[qq * 4 + 0], dup2(wv.x), a2);
                a2 = f2fma(xin2[qq * 4 + 1], dup2(wv.y), a2);
                a2 = f2fma(xin2[qq * 4 + 2], dup2(wv.z), a2);
                a2 = f2fma(xin2[qq * 4 + 3], dup2(wv.w), a2);
            }
            *(ull*)(g_xv + (((size_t)b * 64 + half * 32 + oc) << 14) + pix) = a2;
        }
    }

    __syncthreads();
    #pragma unroll
    for (int off = 16; off; off >>= 1)
        #pragma unroll
        for (int g4 = 0; g4 < 4; g4++) {
            lsum[g4] += __shfl_xor_sync(0xffffffffu, lsum[g4], off);
            lsq[g4]  += __shfl_xor_sync(0xffffffffu, lsq[g4],  off);
        }
    const int wid = tid >> 5, lane = tid & 31;
    if (lane == 0) {
        #pragma unroll
        for (int g4 = 0; g4 < 4; g4++) {
            sm[wid * 8 + g4] = lsum[g4];
            sm[wid * 8 + 4 + g4] = lsq[g4];
        }
    }
    __syncthreads();
    if (tid < 8) {
        float s = 0.f;
        #pragma unroll
        for (int w = 0; w < 8; w++) s += sm[w * 8 + tid];
        int slot = (b * 32 + blockIdx.y * 4 + blockIdx.x) * 16;
        int e = (tid < 4) ? (half * 4 + tid) : (8 + half * 4 + tid - 4);
        g_gnpart[slot + e] = s;
    }
    __syncthreads();

    if (tid == 0) {
        __threadfence();
        unsigned old = atomicAdd(&g_ctrA, 1u);
        isLast = (old == 511u);
    }
    __syncthreads();
    if (isLast) {
        int idx = tid >> 2, k = tid & 3;
        int bb = idx >> 3, gg = idx & 7;
        float s = 0.f, q = 0.f;
        #pragma unroll
        for (int t = 0; t < 8; t++) {
            int tile = k * 8 + t;
            s += *(volatile const float*)&g_gnpart[(bb * 32 + tile) * 16 + gg];
            q += *(volatile const float*)&g_gnpart[(bb * 32 + tile) * 16 + 8 + gg];
        }
        #pragma unroll
        for (int off = 2; off; off >>= 1) {
            s += __shfl_xor_sync(0xffffffffu, s, off);
            q += __shfl_xor_sync(0xffffffffu, q, off);
        }
        if (k == 0) {
            const float inv_n = 1.f / 147456.f;
            float m = s * inv_n;
            float v = fmaf(q, inv_n, -m * m);
            g_gnstat[idx * 2] = m;
            g_gnstat[idx * 2 + 1] = rsqrtf(v + 1e-5f);
        }
        if (tid == 0) g_ctrA = 0;
    }
}

// ---------------- passB (exact R12) --------------------------------------------------
#define ST  0
#define SC  8
#define GW  264
#define GB  300
#define XTB 336
#define SMEMB ((XTB + XT_SZ_H) * 4)

__global__ void __launch_bounds__(256, 2) passB(
    float* __restrict__ out, const float* __restrict__ gnw,
    const float* __restrict__ gnb, const float* __restrict__ wdu1,
    const float* __restrict__ wdu2)
{
    extern __shared__ float sm[];
    __shared__ bool isLast;
    __shared__ float smm[512], t4s[32];
    const int tid = threadIdx.x;
    const int b = blockIdx.z >> 1, half = blockIdx.z & 1;
    const int ty0 = blockIdx.y * TILE_H, tx0 = blockIdx.x * TILE_W;

    float* xt = sm + XTB;
    const float* xvb = g_xv + (size_t)b * 64 * HW + ((size_t)half << 19);
    for (int i = tid; i < XT_HALF; i += 256) {
        int c = i / CSTR, r = i - c * CSTR, yy = r / XSTR, xx = r - yy * XSTR;
        int gy = ty0 + yy - 1, gx = tx0 + xx - 1;
        bool ok = ((unsigned)gy < 128u) && ((unsigned)gx < 128u);
        int cgy = min(max(gy, 0), 127), cgx = min(max(gx, 0), 127);
        cpa4(xt + i, xvb + (c << 14) + (cgy << 7) + cgx, ok ? 4 : 0);
    }
    cpa_commit();
    for (int i = XT_HALF + tid; i < XT_SZ_H; i += 256) {
        int c = i / CSTR, r = i - c * CSTR, yy = r / XSTR, xx = r - yy * XSTR;
        int gy = ty0 + yy - 1, gx = tx0 + xx - 1;
        bool ok = ((unsigned)gy < 128u) && ((unsigned)gx < 128u);
        int cgy = min(max(gy, 0), 127), cgx = min(max(gx, 0), 127);
        cpa4(xt + i, xvb + (c << 14) + (cgy << 7) + cgx, ok ? 4 : 0);
    }
    cpa_commit();

    if (tid < 8) sm[ST + tid] = g_gnstat[b * 16 + half * 8 + tid];
    if (tid < 256) sm[SC + tid] = 0.f;
    if (tid >= 128 && tid < 164) sm[GW + tid - 128] = gnw[half * 36 + tid - 128];
    if (tid >= 192 && tid < 228) sm[GB + tid - 192] = gnb[half * 36 + tid - 192];

    cpa_wait1();
    __syncthreads();

    const int lty = tid >> 4, lx0 = (tid & 15) << 1;
    const int pix = ((ty0 + lty) << 7) + tx0 + lx0;
    const int wid = tid >> 5;

    #pragma unroll 1
    for (int g4 = 0; g4 < 4; g4++) {
        if (g4 == 2) {
            cpa_wait0();
            __syncthreads();
        }
        float mean = sm[ST + g4 * 2], rstd = sm[ST + g4 * 2 + 1];
        ull bw[9];
        #pragma unroll
        for (int t = 0; t < 9; t++) {
            int o2 = half * 36 + g4 * 9 + t;
            float2 raw = *(const float2*)(g_wraw + (((size_t)b * 72 + o2) << 14) + pix);
            float gw = sm[GW + g4 * 9 + t], gb = sm[GB + g4 * 9 + t];
            float w0 = fmaf((raw.x - mean) * rstd, gw, gb);
            float w1 = fmaf((raw.y - mean) * rstd, gw, gb);
            bw[t] = pk2(w0, w1);
        }
        #pragma unroll 1
        for (int cc = 0; cc < 8; cc++) {
            int cl = g4 * 8 + cc;
            const float* pb = xt + cl * CSTR + lty * XSTR + lx0;
            ull a2 = 0ull;
            #pragma unroll
            for (int dy = 0; dy < 3; dy++) {
                ull A = *(const ull*)(pb + dy * XSTR);
                ull B = *(const ull*)(pb + dy * XSTR + 2);
                float a0, a1, b0, b1;
                upk2(A, a0, a1); upk2(B, b0, b1);
                a2 = f2fma(A,           bw[dy * 3 + 0], a2);
                a2 = f2fma(pk2(a1, b0), bw[dy * 3 + 1], a2);
                a2 = f2fma(B,           bw[dy * 3 + 2], a2);
            }
            *(ull*)(out + (((size_t)b * 64 + half * 32 + cl) << 14) + pix) = a2;
            float a0, a1; upk2(a2, a0, a1);
            float s = a0 + a1;
            #pragma unroll
            for (int off = 16; off; off >>= 1)
                s += __shfl_xor_sync(0xffffffffu, s, off);
            if ((tid & 31) == 0) sm[SC + wid * 32 + cl] += s;
        }
    }
    __syncthreads();
    if (tid < 32) {
        float s = 0.f;
        #pragma unroll
        for (int w = 0; w < 8; w++) s += sm[SC + w * 32 + tid];
        g_chanpart[(b * 32 + blockIdx.y * 4 + blockIdx.x) * 64 + half * 32 + tid] = s;
    }
    __syncthreads();

    if (tid == 0) {
        __threadfence();
        unsigned old = atomicAdd(&g_ctrB, 1u);
        isLast = (old == 511u);
    }
    __syncthreads();
    if (isLast) {
        #pragma unroll
        for (int rep = 0; rep < 2; rep++) {
            int idx = rep * 256 + tid;
            int bb = idx >> 6, c = idx & 63;
            float s = 0.f;
            #pragma unroll
            for (int t = 0; t < 32; t++)
                s += *(volatile const float*)&g_chanpart[(bb * 32 + t) * 64 + c];
            smm[idx] = s * (1.f / 16384.f);
        }
        __syncthreads();
        if (tid < 32) {
            int bb = tid >> 2, h = tid & 3;
            float a = 0.f;
            #pragma unroll
            for (int i = 0; i < 64; i++)
                a = fmaf(smm[bb * 64 + i], __ldg(wdu1 + h * 64 + i), a);
            t4s[tid] = fmaxf(a, 0.f);
        }
        __syncthreads();
        #pragma unroll
        for (int rep = 0; rep < 2; rep++) {
            int idx = rep * 256 + tid;
            int bb = idx >> 6, c = idx & 63;
            float a = 0.f;
            #pragma unroll
            for (int j = 0; j < 4; j++)
                a = fmaf(t4s[bb * 4 + j], __ldg(wdu2 + c * 4 + j), a);
            g_yscale[idx] = 1.f / (1.f + expf(-a));
        }
        if (tid == 0) g_ctrB = 0;
    }
}

// ---------------- final scale -----------------------------------------------------
__global__ void scaleK(float* __restrict__ out)
{
    int i = blockIdx.x * blockDim.x + threadIdx.x;
    float4* p = (float4*)out;
    float s = g_yscale[i >> 12];
    float4 v = p[i];
    v.x *= s; v.y *= s; v.z *= s; v.w *= s;
    p[i] = v;
}

// ---------------- launcher ---------------------------------------------------------
extern "C" void kernel_launch(void* const* d_in, const int* in_sizes, int n_in,
                              void* d_out, int out_size)
{
    const float* x    = (const float*)d_in[0];
    const float* wkey = (const float*)d_in[1];
    const float* we1  = (const float*)d_in[2];
    const float* we2  = (const float*)d_in[3];
    const float* be2  = (const float*)d_in[4];
    const float* gnw  = (const float*)d_in[5];
    const float* gnb  = (const float*)d_in[6];
    const float* wc1  = (const float*)d_in[7];
    const float* wdu1 = (const float*)d_in[8];
    const float* wdu2 = (const float*)d_in[9];
    float* out = (float*)d_out;

    cudaFuncSetAttribute(passA, cudaFuncAttributeMaxDynamicSharedMemorySize, SMEMA);
    cudaFuncSetAttribute(passB, cudaFuncAttributeMaxDynamicSharedMemorySize, SMEMB);

    dim3 grid(4, 8, 16);
    passA<<<grid, 256, SMEMA>>>(x, wkey, we1, we2, be2, wc1);
    passB<<<grid, 256, SMEMB>>>(out, gnw, gnb, wdu1, wdu2);
    scaleK<<<8192, 256>>>(out);
}

// round 16
// speedup vs baseline: 1.7538x; 1.0335x over previous
#include <cuda_runtime.h>

#define HW 16384
#define TILE_W 32
#define TILE_H 16
#define XSTR 34            // EVEN padded row stride -> 8B-aligned pairs
#define CSTR 612           // 18 * 34
#define XT_SZ_H 19584      // 32 channels * 612
#define XT_HALF 9792       // 16 channels * 612

typedef unsigned long long ull;

// ---------------- f32x2 helpers ------------------------------------------------
__device__ __forceinline__ ull pk2(float lo, float hi) {
    ull r; asm("mov.b64 %0,{%1,%2};" : "=l"(r) : "f"(lo), "f"(hi)); return r;
}
__device__ __forceinline__ ull dup2(float v) { return pk2(v, v); }
__device__ __forceinline__ void upk2(ull v, float& lo, float& hi) {
    asm("mov.b64 {%0,%1},%2;" : "=f"(lo), "=f"(hi) : "l"(v));
}
__device__ __forceinline__ ull f2fma(ull a, ull b, ull c) {
    ull d; asm("fma.rn.f32x2 %0,%1,%2,%3;" : "=l"(d) : "l"(a), "l"(b), "l"(c)); return d;
}
__device__ __forceinline__ ull f2add(ull a, ull b) {
    ull d; asm("add.rn.f32x2 %0,%1,%2;" : "=l"(d) : "l"(a), "l"(b)); return d;
}
__device__ __forceinline__ ull f2relu(ull v) {
    float lo, hi; upk2(v, lo, hi);
    return pk2(fmaxf(lo, 0.f), fmaxf(hi, 0.f));
}

// ---------------- cp.async helpers ---------------------------------------------
__device__ __forceinline__ void cpa4(void* sdst, const void* gsrc, int szbytes) {
    unsigned saddr = (unsigned)__cvta_generic_to_shared(sdst);
    asm volatile("cp.async.ca.shared.global [%0], [%1], 4, %2;"
                 :: "r"(saddr), "l"(gsrc), "r"(szbytes));
}
__device__ __forceinline__ void cpa_commit() {
    asm volatile("cp.async.commit_group;");
}
__device__ __forceinline__ void cpa_wait1() {
    asm volatile("cp.async.wait_group 1;" ::: "memory");
}
__device__ __forceinline__ void cpa_wait0() {
    asm volatile("cp.async.wait_group 0;" ::: "memory");
}

// ---------------- scratch ----------------------------------------------------
__device__ float g_wraw[8 * 72 * HW];
__device__ float g_xv[8 * 64 * HW];
__device__ float g_gnpart[256 * 16];
__device__ float g_gnstat[64 * 2];
__device__ float g_chanpart[256 * 64];
__device__ float g_yscale[512];
__device__ unsigned g_ctrA = 0;
__device__ unsigned g_ctrB = 0;

// ---------------- passA smem layout (float offsets), per half ----------------
#define WKd 0              // 2304: oc-paired key weights
#define WE1 2304           // 1024: o-pair interleaved
#define WE2 3328           // 576
#define BE2 3904           // 36 (pad 40)
#define WC1 3944           // 1024
#define XTA 4968
#define SMEMA ((XTA + XT_SZ_H) * 4)

__global__ void __launch_bounds__(256, 2) passA(
    const float* __restrict__ x, const float* __restrict__ wkey,
    const float* __restrict__ we1, const float* __restrict__ we2,
    const float* __restrict__ be2, const float* __restrict__ wc1)
{
    extern __shared__ float sm[];
    __shared__ bool isLast;
    const int tid = threadIdx.x;
    const int b = blockIdx.z >> 1, half = blockIdx.z & 1;
    const int ty0 = blockIdx.y * TILE_H, tx0 = blockIdx.x * TILE_W;
    const float* xb = x + (size_t)b * 64 * HW + ((size_t)half << 19);
    float* xt = sm + XTA;

    // ---- group 0: tile channels 0..15 + all weights ----
    for (int i = tid; i < XT_HALF; i += 256) {
        int c = i / CSTR, r = i - c * CSTR, yy = r / XSTR, xx = r - yy * XSTR;
        int gy = ty0 + yy - 1, gx = tx0 + xx - 1;
        bool ok = ((unsigned)gy < 128u) && ((unsigned)gx < 128u);
        int cgy = min(max(gy, 0), 127), cgx = min(max(gx, 0), 127);
        cpa4(xt + i, xb + (c << 14) + (cgy << 7) + cgx, ok ? 4 : 0);
    }
    for (int i = tid; i < 2304; i += 256) {
        int w18 = i / 18, r = i - w18 * 18;
        int t = r >> 1, s = r & 1;
        int ocp = w18 & 3, gci = w18 >> 2;
        int ci = gci & 7, g4 = gci >> 3;
        cpa4(sm + WKd + i, wkey + (half * 32 + g4 * 8 + ocp * 2 + s) * 72 + ci * 9 + t, 4);
    }
    for (int i = tid; i < 1024; i += 256) {
        int m = i >> 5, r = i & 31, p = r >> 2, q = r & 3;
        int o = 2 * p + (q & 1), s = q >> 1;
        cpa4(sm + WE1 + i, we1 + half * 1024 + o * 64 + m * 2 + s, 4);
    }
    for (int i = tid; i < 576; i += 256) cpa4(sm + WE2 + i, we2 + half * 576 + i, 4);
    if (tid < 36) cpa4(sm + BE2 + tid, be2 + half * 36 + tid, 4);
    for (int i = tid; i < 1024; i += 256) cpa4(sm + WC1 + i, wc1 + half * 1024 + i, 4);
    cpa_commit();

    // ---- group 1: tile channels 16..31 ----
    for (int i = XT_HALF + tid; i < XT_SZ_H; i += 256) {
        int c = i / CSTR, r = i - c * CSTR, yy = r / XSTR, xx = r - yy * XSTR;
        int gy = ty0 + yy - 1, gx = tx0 + xx - 1;
        bool ok = ((unsigned)gy < 128u) && ((unsigned)gx < 128u);
        int cgy = min(max(gy, 0), 127), cgx = min(max(gx, 0), 127);
        cpa4(xt + i, xb + (c << 14) + (cgy << 7) + cgx, ok ? 4 : 0);
    }
    cpa_commit();

    cpa_wait1();
    __syncthreads();

    const int lty = tid >> 4, lx0 = (tid & 15) << 1;
    const int pix = ((ty0 + lty) << 7) + tx0 + lx0;

    ull aP0[8], aP1[8];
    #pragma unroll
    for (int p = 0; p < 8; p++) { aP0[p] = 0ull; aP1[p] = 0ull; }

    #pragma unroll 1
    for (int g4 = 0; g4 < 4; g4++) {
        if (g4 == 2) {
            cpa_wait0();
            __syncthreads();
        }
        ull kk2[8];
        #pragma unroll
        for (int i = 0; i < 8; i++) kk2[i] = 0ull;

        #pragma unroll 1
        for (int ci = 0; ci < 8; ci++) {
            const float* pb = xt + (g4 * 8 + ci) * CSTR + lty * XSTR + lx0;
            ull dp[12];
            #pragma unroll
            for (int dy = 0; dy < 3; dy++) {
                ull A = *(const ull*)(pb + dy * XSTR);
                ull B = *(const ull*)(pb + dy * XSTR + 2);
                float p0, p1, p2, p3;
                upk2(A, p0, p1); upk2(B, p2, p3);
                dp[dy * 4 + 0] = dup2(p0); dp[dy * 4 + 1] = dup2(p1);
                dp[dy * 4 + 2] = dup2(p2); dp[dy * 4 + 3] = dup2(p3);
            }
            const ull* wd = (const ull*)(sm + WKd) + (g4 * 8 + ci) * 36;
            #pragma unroll
            for (int ocp = 0; ocp < 4; ocp++) {
                ull kA = kk2[ocp], kB = kk2[4 + ocp];
                #pragma unroll
                for (int dy = 0; dy < 3; dy++)
                    #pragma unroll
                    for (int dx = 0; dx < 3; dx++) {
                        ull w = wd[ocp * 9 + dy * 3 + dx];
                        kA = f2fma(dp[dy * 4 + dx],     w, kA);
                        kB = f2fma(dp[dy * 4 + dx + 1], w, kB);
                    }
                kk2[ocp] = kA; kk2[4 + ocp] = kB;
            }
        }
        float k0[8], k1[8];
        #pragma unroll
        for (int ocp = 0; ocp < 4; ocp++) {
            upk2(kk2[ocp],     k0[2 * ocp], k0[2 * ocp + 1]);
            upk2(kk2[4 + ocp], k1[2 * ocp], k1[2 * ocp + 1]);
        }
        #pragma unroll 1
        for (int ci = 0; ci < 8; ci++) {
            const float* ctr = xt + (g4 * 8 + ci) * CSTR + (lty + 1) * XSTR + lx0 + 1;
            ull dx0 = dup2(ctr[0]), dx1 = dup2(ctr[1]);
            ull dk0 = dup2(fmaxf(k0[ci], 0.f)), dk1 = dup2(fmaxf(k1[ci], 0.f));
            const ulonglong2* w1 = (const ulonglong2*)(sm + WE1 + ((g4 * 8 + ci) << 5));
            #pragma unroll
            for (int p = 0; p < 8; p++) {
                ulonglong2 w = w1[p];
                aP0[p] = f2fma(dx0, w.x, f2fma(dk0, w.y, aP0[p]));
                aP1[p] = f2fma(dx1, w.x, f2fma(dk1, w.y, aP1[p]));
            }
        }
    }
    ull acc2[16];
    #pragma unroll
    for (int p = 0; p < 8; p++) {
        float a00, a01, a10, a11;
        upk2(aP0[p], a00, a01);
        upk2(aP1[p], a10, a11);
        acc2[2 * p]     = pk2(fmaxf(a00, 0.f), fmaxf(a10, 0.f));
        acc2[2 * p + 1] = pk2(fmaxf(a01, 0.f), fmaxf(a11, 0.f));
    }

    float lsum[4], lsq[4];
    #pragma unroll
    for (int g4 = 0; g4 < 4; g4++) {
        ull s2 = 0ull, q2 = 0ull;
        #pragma unroll
        for (int j = 0; j < 9; j++) {
            const int o2l = g4 * 9 + j;
            const float4* w2 = (const float4*)(sm + WE2 + o2l * 16);
            ull a2 = dup2(sm[BE2 + o2l]);
            #pragma unroll
            for (int qq = 0; qq < 4; qq++) {
                float4 w = w2[qq];
                a2 = f2fma(acc2[qq * 4 + 0], dup2(w.x), a2);
                a2 = f2fma(acc2[qq * 4 + 1], dup2(w.y), a2);
                a2 = f2fma(acc2[qq * 4 + 2], dup2(w.z), a2);
                a2 = f2fma(acc2[qq * 4 + 3], dup2(w.w), a2);
            }
            *(ull*)(g_wraw + (((size_t)b * 72 + half * 36 + o2l) << 14) + pix) = a2;
            s2 = f2add(s2, a2);
            q2 = f2fma(a2, a2, q2);
        }
        float slo, shi, qlo, qhi;
        upk2(s2, slo, shi); upk2(q2, qlo, qhi);
        lsum[g4] = slo + shi; lsq[g4] = qlo + qhi;
    }

    {
        ull xin2[32];
        #pragma unroll
        for (int ic = 0; ic < 32; ic++) {
            const float* ctr = xt + ic * CSTR + (lty + 1) * XSTR + lx0 + 1;
            xin2[ic] = pk2(ctr[0], ctr[1]);
        }
        #pragma unroll 1
        for (int oc = 0; oc < 32; oc++) {
            const float4* w = (const float4*)(sm + WC1 + (oc << 5));
            ull a2 = 0ull;
            #pragma unroll
            for (int qq = 0; qq < 8; qq++) {
                float4 wv = w[qq];
                a2 = f2fma(xin2[qq * 4 + 0], dup2(wv.x), a2);
                a2 = f2fma(xin2[qq * 4 + 1], dup2(wv.y), a2);
                a2 = f2fma(xin2[qq * 4 + 2], dup2(wv.z), a2);
                a2 = f2fma(xin2[qq * 4 + 3], dup2(wv.w), a2);
            }
            *(ull*)(g_xv + (((size_t)b * 64 + half * 32 + oc) << 14) + pix) = a2;
        }
    }

    __syncthreads();
    #pragma unroll
    for (int off = 16; off; off >>= 1)
        #pragma unroll
        for (int g4 = 0; g4 < 4; g4++) {
            lsum[g4] += __shfl_xor_sync(0xffffffffu, lsum[g4], off);
            lsq[g4]  += __shfl_xor_sync(0xffffffffu, lsq[g4],  off);
        }
    const int wid = tid >> 5, lane = tid & 31;
    if (lane == 0) {
        #pragma unroll
        for (int g4 = 0; g4 < 4; g4++) {
            sm[wid * 8 + g4] = lsum[g4];
            sm[wid * 8 + 4 + g4] = lsq[g4];
        }
    }
    __syncthreads();
    if (tid < 8) {
        float s = 0.f;
        #pragma unroll
        for (int w = 0; w < 8; w++) s += sm[w * 8 + tid];
        int slot = (b * 32 + blockIdx.y * 4 + blockIdx.x) * 16;
        int e = (tid < 4) ? (half * 4 + tid) : (8 + half * 4 + tid - 4);
        g_gnpart[slot + e] = s;
    }
    __syncthreads();

    if (tid == 0) {
        __threadfence();
        unsigned old = atomicAdd(&g_ctrA, 1u);
        isLast = (old == 511u);
    }
    __syncthreads();
    if (isLast) {
        int idx = tid >> 2, k = tid & 3;
        int bb = idx >> 3, gg = idx & 7;
        float s = 0.f, q = 0.f;
        #pragma unroll
        for (int t = 0; t < 8; t++) {
            int tile = k * 8 + t;
            s += *(volatile const float*)&g_gnpart[(bb * 32 + tile) * 16 + gg];
            q += *(volatile const float*)&g_gnpart[(bb * 32 + tile) * 16 + 8 + gg];
        }
        #pragma unroll
        for (int off = 2; off; off >>= 1) {
            s += __shfl_xor_sync(0xffffffffu, s, off);
            q += __shfl_xor_sync(0xffffffffu, q, off);
        }
        if (k == 0) {
            const float inv_n = 1.f / 147456.f;
            float m = s * inv_n;
            float v = fmaf(q, inv_n, -m * m);
            g_gnstat[idx * 2] = m;
            g_gnstat[idx * 2 + 1] = rsqrtf(v + 1e-5f);
        }
        if (tid == 0) g_ctrA = 0;
    }
}

// ---------------- passB (R12 + pipelined wraw loads) ----------------------------
#define ST  0
#define SC  8
#define GW  264
#define GB  300
#define XTB 336
#define SMEMB ((XTB + XT_SZ_H) * 4)

__global__ void __launch_bounds__(256, 2) passB(
    float* __restrict__ out, const float* __restrict__ gnw,
    const float* __restrict__ gnb, const float* __restrict__ wdu1,
    const float* __restrict__ wdu2)
{
    extern __shared__ float sm[];
    __shared__ bool isLast;
    __shared__ float smm[512], t4s[32];
    const int tid = threadIdx.x;
    const int b = blockIdx.z >> 1, half = blockIdx.z & 1;
    const int ty0 = blockIdx.y * TILE_H, tx0 = blockIdx.x * TILE_W;

    float* xt = sm + XTB;
    const float* xvb = g_xv + (size_t)b * 64 * HW + ((size_t)half << 19);
    for (int i = tid; i < XT_HALF; i += 256) {
        int c = i / CSTR, r = i - c * CSTR, yy = r / XSTR, xx = r - yy * XSTR;
        int gy = ty0 + yy - 1, gx = tx0 + xx - 1;
        bool ok = ((unsigned)gy < 128u) && ((unsigned)gx < 128u);
        int cgy = min(max(gy, 0), 127), cgx = min(max(gx, 0), 127);
        cpa4(xt + i, xvb + (c << 14) + (cgy << 7) + cgx, ok ? 4 : 0);
    }
    cpa_commit();
    for (int i = XT_HALF + tid; i < XT_SZ_H; i += 256) {
        int c = i / CSTR, r = i - c * CSTR, yy = r / XSTR, xx = r - yy * XSTR;
        int gy = ty0 + yy - 1, gx = tx0 + xx - 1;
        bool ok = ((unsigned)gy < 128u) && ((unsigned)gx < 128u);
        int cgy = min(max(gy, 0), 127), cgx = min(max(gx, 0), 127);
        cpa4(xt + i, xvb + (c << 14) + (cgy << 7) + cgx, ok ? 4 : 0);
    }
    cpa_commit();

    if (tid < 8) sm[ST + tid] = g_gnstat[b * 16 + half * 8 + tid];
    if (tid < 256) sm[SC + tid] = 0.f;
    if (tid >= 128 && tid < 164) sm[GW + tid - 128] = gnw[half * 36 + tid - 128];
    if (tid >= 192 && tid < 228) sm[GB + tid - 192] = gnb[half * 36 + tid - 192];

    const int lty = tid >> 4, lx0 = (tid & 15) << 1;
    const int pix = ((ty0 + lty) << 7) + tx0 + lx0;
    const int wid = tid >> 5;
    const float* wrb = g_wraw + (((size_t)b * 72 + half * 36) << 14) + pix;

    // prefetch g4=0's raw kernel values BEFORE the tile wait (overlaps fill)
    float2 raw[9];
    #pragma unroll
    for (int t = 0; t < 9; t++)
        raw[t] = __ldg((const float2*)(wrb + ((size_t)t << 14)));

    cpa_wait1();
    __syncthreads();

    #pragma unroll 1
    for (int g4 = 0; g4 < 4; g4++) {
        if (g4 == 2) {
            cpa_wait0();
            __syncthreads();
        }
        float mean = sm[ST + g4 * 2], rstd = sm[ST + g4 * 2 + 1];
        ull bw[9];
        #pragma unroll
        for (int t = 0; t < 9; t++) {
            float gw = sm[GW + g4 * 9 + t], gb = sm[GB + g4 * 9 + t];
            float w0 = fmaf((raw[t].x - mean) * rstd, gw, gb);
            float w1 = fmaf((raw[t].y - mean) * rstd, gw, gb);
            bw[t] = pk2(w0, w1);
        }
        // prefetch next group's raw values; latency hidden by the cc loop below
        if (g4 < 3) {
            #pragma unroll
            for (int t = 0; t < 9; t++)
                raw[t] = __ldg((const float2*)(wrb + ((size_t)((g4 + 1) * 9 + t) << 14)));
        }
        #pragma unroll 1
        for (int cc = 0; cc < 8; cc++) {
            int cl = g4 * 8 + cc;
            const float* pb = xt + cl * CSTR + lty * XSTR + lx0;
            ull a2 = 0ull;
            #pragma unroll
            for (int dy = 0; dy < 3; dy++) {
                ull A = *(const ull*)(pb + dy * XSTR);
                ull B = *(const ull*)(pb + dy * XSTR + 2);
                float a0, a1, b0, b1;
                upk2(A, a0, a1); upk2(B, b0, b1);
                a2 = f2fma(A,           bw[dy * 3 + 0], a2);
                a2 = f2fma(pk2(a1, b0), bw[dy * 3 + 1], a2);
                a2 = f2fma(B,           bw[dy * 3 + 2], a2);
            }
            *(ull*)(out + (((size_t)b * 64 + half * 32 + cl) << 14) + pix) = a2;
            float a0, a1; upk2(a2, a0, a1);
            float s = a0 + a1;
            #pragma unroll
            for (int off = 16; off; off >>= 1)
                s += __shfl_xor_sync(0xffffffffu, s, off);
            if ((tid & 31) == 0) sm[SC + wid * 32 + cl] += s;
        }
    }
    __syncthreads();
    if (tid < 32) {
        float s = 0.f;
        #pragma unroll
        for (int w = 0; w < 8; w++) s += sm[SC + w * 32 + tid];
        g_chanpart[(b * 32 + blockIdx.y * 4 + blockIdx.x) * 64 + half * 32 + tid] = s;
    }
    __syncthreads();

    if (tid == 0) {
        __threadfence();
        unsigned old = atomicAdd(&g_ctrB, 1u);
        isLast = (old == 511u);
    }
    __syncthreads();
    if (isLast) {
        #pragma unroll
        for (int rep = 0; rep < 2; rep++) {
            int idx = rep * 256 + tid;
            int bb = idx >> 6, c = idx & 63;
            float s = 0.f;
            #pragma unroll
            for (int t = 0; t < 32; t++)
                s += *(volatile const float*)&g_chanpart[(bb * 32 + t) * 64 + c];
            smm[idx] = s * (1.f / 16384.f);
        }
        __syncthreads();
        if (tid < 32) {
            int bb = tid >> 2, h = tid & 3;
            float a = 0.f;
            #pragma unroll
            for (int i = 0; i < 64; i++)
                a = fmaf(smm[bb * 64 + i], __ldg(wdu1 + h * 64 + i), a);
            t4s[tid] = fmaxf(a, 0.f);
        }
        __syncthreads();
        #pragma unroll
        for (int rep = 0; rep < 2; rep++) {
            int idx = rep * 256 + tid;
            int bb = idx >> 6, c = idx & 63;
            float a = 0.f;
            #pragma unroll
            for (int j = 0; j < 4; j++)
                a = fmaf(t4s[bb * 4 + j], __ldg(wdu2 + c * 4 + j), a);
            g_yscale[idx] = 1.f / (1.f + expf(-a));
        }
        if (tid == 0) g_ctrB = 0;
    }
}

// ---------------- final scale -----------------------------------------------------
__global__ void scaleK(float* __restrict__ out)
{
    int i = blockIdx.x * blockDim.x + threadIdx.x;
    float4* p = (float4*)out;
    float s = g_yscale[i >> 12];
    float4 v = p[i];
    v.x *= s; v.y *= s; v.z *= s; v.w *= s;
    p[i] = v;
}

// ---------------- launcher ---------------------------------------------------------
extern "C" void kernel_launch(void* const* d_in, const int* in_sizes, int n_in,
                              void* d_out, int out_size)
{
    const float* x    = (const float*)d_in[0];
    const float* wkey = (const float*)d_in[1];
    const float* we1  = (const float*)d_in[2];
    const float* we2  = (const float*)d_in[3];
    const float* be2  = (const float*)d_in[4];
    const float* gnw  = (const float*)d_in[5];
    const float* gnb  = (const float*)d_in[6];
    const float* wc1  = (const float*)d_in[7];
    const float* wdu1 = (const float*)d_in[8];
    const float* wdu2 = (const float*)d_in[9];
    float* out = (float*)d_out;

    cudaFuncSetAttribute(passA, cudaFuncAttributeMaxDynamicSharedMemorySize, SMEMA);
    cudaFuncSetAttribute(passB, cudaFuncAttributeMaxDynamicSharedMemorySize, SMEMB);

    dim3 grid(4, 8, 16);
    passA<<<grid, 256, SMEMA>>>(x, wkey, we1, we2, be2, wc1);
    passB<<<grid, 256, SMEMB>>>(out, gnw, gnb, wdu1, wdu2);
    scaleK<<<8192, 256>>>(out);
}